// round 10
// baseline (speedup 1.0000x reference)
#include <cuda_runtime.h>
#include <cstdint>

#define F_INF __int_as_float(0x7f800000)

#define NN 2
#define ANG 5
#define AN2 25
#define CH 32
#define KN 6
#define PSHL 8
#define HH 128
#define WWD 128
#define PNH 16                 // WWD / PSHL
#define BB (NN*PNH)            // 32
#define CM (CH*ANG*PSHL)       // 1280
#define PP (ANG*HH)            // 640
#define NE (NN*ANG*HH)         // 1280 epi images
#define IMG (HH*WWD)           // 16384

// ---------------- scratch (device globals; no allocations) ----------------
__device__ float  g_M[(size_t)BB*CM*PP];        // 104.9 MB
__device__ float  g_G[(size_t)BB*PP*PP];        // 52.4 MB (full, mirrored)
__device__ float  g_SQF[BB*PP];                 // XLA-tree (fused fma) sq
__device__ int    g_IDX[BB*PP*KN];
__device__ float  g_O1[(size_t)NE*CH*ANG*WWD];  // 104.9 MB conv1 output

// ================= kernel 1: permute lf_fea -> M ==========================
// M[b=(n,pnh)][cm=(c,v,psh)][p=(u,h)] = lf[(n,u,v)][c][h][pnh*8+psh]
__global__ void k_permute(const float* __restrict__ lf) {
    int bid = blockIdx.x;                 // (a0, c, htile)
    int ht  = bid & 3;
    int c   = (bid >> 2) & 31;
    int a0  = bid >> 7;                   // 0..49
    int n = a0 / AN2, r = a0 % AN2, u = r / ANG, v = r % ANG;
    __shared__ float s[32][129];
    const float* src = lf + ((size_t)(a0*CH + c) << 14) + (size_t)(ht*32)*WWD;
    for (int i = threadIdx.x; i < 32*128; i += 256) {
        int hh = i >> 7, w = i & 127;
        s[hh][w] = src[i];
    }
    __syncthreads();
    int cmBase = c*40 + v*8;
    for (int i = threadIdx.x; i < 128*32; i += 256) {
        int w = i >> 5, hh = i & 31;
        int pnh = w >> 3, psh = w & 7;
        int b = n*PNH + pnh;
        int cm = cmBase + psh;
        g_M[((size_t)b*CM + cm)*PP + u*HH + ht*32 + hh] = s[hh][w];
    }
}

// ================= kernel 1b: sq — XLA GPU column-reduce, fused fma =======
// partial[s] over c = s + 32j ascending via fma.rn; shfl_down-style tree.
__global__ void k_sq(void) {
    int b = blockIdx.y;
    int q = blockIdx.x*128 + threadIdx.x;
    const float* Mb = g_M + (size_t)b*CM*PP + q;
    float partial[32];
    #pragma unroll
    for (int s = 0; s < 32; s++) partial[s] = 0.f;
    #pragma unroll 2
    for (int j = 0; j < 40; j++) {
        #pragma unroll
        for (int s = 0; s < 32; s++) {
            float m = Mb[(size_t)(j*32 + s)*PP];
            partial[s] = __fmaf_rn(m, m, partial[s]);
        }
    }
    #pragma unroll
    for (int off = 16; off > 0; off >>= 1)
        #pragma unroll
        for (int s = 0; s < 16; s++)
            if (s < off)
                partial[s] = __fadd_rn(partial[s], partial[s + off]);
    g_SQF[b*PP + q] = partial[0];
}

// ================= kernel 2: Gram — chunked tensor-core-accum emulation ===
// Emulates Blackwell cuBLAS FP32 path: per 16-k chunk the product sum is
// internally exact (fp64 here), folded into the fp32 accumulator with ONE
// rounding per chunk, ascending k:  acc32 = fl32(acc32 + chunk_exact).
__global__ __launch_bounds__(256) void k_gram(void) {
    int b = blockIdx.y;
    int t = blockIdx.x;                   // 0..54 -> (ti,tj), ti<=tj
    int ti = 0, rem = t;
    while (rem >= 10 - ti) { rem -= 10 - ti; ti++; }
    int tj = ti + rem;
    __shared__ float As[16][68];
    __shared__ float Bs[16][68];
    const float* Mb = g_M + (size_t)b*CM*PP;
    int tid = threadIdx.x;
    int tx = tid & 15, ty = tid >> 4;
    int pi0 = ti*64, qj0 = tj*64;
    float acc32[4][4] = {};
    int lr = tid >> 4;                    // row in k-chunk
    int li = (tid & 15) * 4;              // col (float4)
    for (int kk = 0; kk < CM; kk += 16) {
        const float* pA = Mb + (size_t)(kk + lr)*PP;
        *(float4*)&As[lr][li] = *(const float4*)&pA[pi0 + li];
        *(float4*)&Bs[lr][li] = *(const float4*)&pA[qj0 + li];
        __syncthreads();
        double ch[4][4] = {};
        #pragma unroll
        for (int s = 0; s < 16; s++) {
            float4 a4 = *(float4*)&As[s][ty*4];
            float4 b4 = *(float4*)&Bs[s][tx*4];
            double ad[4] = {a4.x, a4.y, a4.z, a4.w};
            double bd[4] = {b4.x, b4.y, b4.z, b4.w};
            #pragma unroll
            for (int i = 0; i < 4; i++)
                #pragma unroll
                for (int j = 0; j < 4; j++)
                    ch[i][j] = fma(ad[i], bd[j], ch[i][j]);
        }
        __syncthreads();
        #pragma unroll
        for (int i = 0; i < 4; i++)
            #pragma unroll
            for (int j = 0; j < 4; j++)
                acc32[i][j] = (float)((double)acc32[i][j] + ch[i][j]);
    }
    float* Gb = g_G + (size_t)b*PP*PP;
    #pragma unroll
    for (int i = 0; i < 4; i++)
        #pragma unroll
        for (int j = 0; j < 4; j++) {
            float v = acc32[i][j];
            int p = pi0 + ty*4 + i, q = qj0 + tx*4 + j;
            Gb[(size_t)p*PP + q] = v;
            Gb[(size_t)q*PP + p] = v;   // mirror (bit-exact: same schedule)
        }
}

// ================= kernel 4: top-K on fp32-quantized d, stable ============
// d = fadd(fadd(sqf_r, sqf_q), -fmul(2, Gf)); ties -> lower index.
__global__ void k_topk(void) {
    int wid  = (blockIdx.x*blockDim.x + threadIdx.x) >> 5;
    int lane = threadIdx.x & 31;
    if (wid >= BB*PP) return;
    int b = wid / PP, r = wid % PP;
    const float* Gr = g_G + (size_t)b*PP*PP + (size_t)r*PP;
    const float* sq = g_SQF + b*PP;
    float sqr = sq[r];
    float lv[6]; int lq[6];
    #pragma unroll
    for (int i = 0; i < 6; i++) { lv[i] = F_INF; lq[i] = 0x7fffffff; }
    for (int q = lane; q < PP; q += 32) {
        float s1 = __fadd_rn(sqr, sq[q]);
        float tg = __fmul_rn(2.0f, Gr[q]);
        float v  = __fadd_rn(s1, -tg);
        bool ins = (v < lv[5]) || (v == lv[5] && q < lq[5]);
        if (ins) {
            lv[5] = v; lq[5] = q;
            #pragma unroll
            for (int i = 5; i > 0; i--) {
                bool sw = (lv[i] < lv[i-1]) || (lv[i] == lv[i-1] && lq[i] < lq[i-1]);
                if (sw) {
                    float tv = lv[i]; lv[i] = lv[i-1]; lv[i-1] = tv;
                    int   tq = lq[i]; lq[i] = lq[i-1]; lq[i-1] = tq;
                }
            }
        }
    }
    for (int t = 0; t < 6; t++) {
        float bv = lv[0]; int bq = lq[0];
        #pragma unroll
        for (int o = 16; o; o >>= 1) {
            float v2 = __shfl_xor_sync(0xffffffffu, bv, o);
            int   q2 = __shfl_xor_sync(0xffffffffu, bq, o);
            if (v2 < bv || (v2 == bv && q2 < bq)) { bv = v2; bq = q2; }
        }
        if (lq[0] == bq) {
            #pragma unroll
            for (int i = 0; i < 5; i++) { lv[i] = lv[i+1]; lq[i] = lq[i+1]; }
            lv[5] = F_INF; lq[5] = 0x7fffffff;
        }
        if (lane == 0) g_IDX[(size_t)wid*KN + t] = bq;
    }
}

// ================= kernel 5: gather + 1x1 conv + leaky -> O1 ==============
__global__ __launch_bounds__(256) void k_conv1(const float* __restrict__ lf,
                                               const float* __restrict__ w1) {
    int e = blockIdx.x;
    int n = e / (ANG*HH);
    int rr_ = e % (ANG*HH);
    int u = rr_ / HH, h = rr_ % HH;
    extern __shared__ float sm[];
    float* Xs = sm;                 // [32][640]
    float* Ws = sm + 32*640;        // [ci][co]
    __shared__ int nbU[PNH][KN], nbH[PNH][KN];
    int tid = threadIdx.x;
    if (tid < PNH*KN) {
        int pnh = tid / KN, k = tid % KN;
        int b = n*PNH + pnh;
        int q = g_IDX[((size_t)b*PP + u*HH + h)*KN + k];
        nbU[pnh][k] = q >> 7;
        nbH[pnh][k] = q & 127;
    }
    int co0  = (tid >> 6) << 3;        // 0,8,16,24
    int col0 = (tid & 63) * 10;        // 0..630
    float acc[8][10] = {};
    for (int k = 0; k < KN; k++) {
        __syncthreads();
        for (int l = tid; l < 1024; l += 256) {
            int ci = l >> 5, co = l & 31;
            Ws[ci*32 + co] = w1[co*(CH*KN) + k*CH + ci];
        }
        for (int seg = tid; seg < 32*5*16; seg += 256) {
            int ci = seg / 80;
            int r2 = seg % 80;
            int v = r2 >> 4, pnh = r2 & 15;
            int uu = nbU[pnh][k], hh2 = nbH[pnh][k];
            const float* src = lf + (((size_t)(n*AN2 + uu*ANG + v)*CH + ci) << 14)
                                  + hh2*WWD + pnh*PSHL;
            float4 x0 = *(const float4*)src;
            float4 x1 = *(const float4*)(src + 4);
            float* dst = &Xs[ci*640 + v*128 + pnh*8];
            *(float4*)dst = x0;
            *(float4*)(dst + 4) = x1;
        }
        __syncthreads();
        #pragma unroll 4
        for (int ci = 0; ci < 32; ci++) {
            float w8[8];
            *(float4*)&w8[0] = *(float4*)&Ws[ci*32 + co0];
            *(float4*)&w8[4] = *(float4*)&Ws[ci*32 + co0 + 4];
            float x10[10];
            #pragma unroll
            for (int s = 0; s < 5; s++)
                *(float2*)&x10[2*s] = *(float2*)&Xs[ci*640 + col0 + 2*s];
            #pragma unroll
            for (int i = 0; i < 8; i++)
                #pragma unroll
                for (int s = 0; s < 10; s++)
                    acc[i][s] += w8[i]*x10[s];
        }
    }
    float* dst = g_O1 + (size_t)e*(CH*ANG*WWD);
    #pragma unroll
    for (int i = 0; i < 8; i++)
        #pragma unroll
        for (int s = 0; s < 10; s++) {
            float x = acc[i][s];
            dst[(co0 + i)*640 + col0 + s] = (x >= 0.f) ? x : 0.1f*x;
        }
}

// ================= kernel 6: concat + 3x3 conv + leaky + out-permute ======
__global__ __launch_bounds__(256,1) void k_conv2(const float* __restrict__ lf,
                                                 const float* __restrict__ w2,
                                                 float* __restrict__ out) {
    int e = blockIdx.x;
    int n = e / (ANG*HH);
    int rr_ = e % (ANG*HH);
    int u = rr_ / HH, h = rr_ % HH;
    extern __shared__ float sm[];
    float* sIn = sm;                      // [64][5][132], data at cols 1..128
    float* ws  = sm + 64*5*132;           // [16][32][9]
    int tid = threadIdx.x;
    for (int l = tid; l < 32*5*128; l += 256) {
        int row = l >> 7, w = l & 127;
        int c = row / 5, v = row % 5;
        sIn[(c*5 + v)*132 + 1 + w] =
            lf[(((size_t)(n*AN2 + u*ANG + v)*CH + c) << 14) + h*WWD + w];
    }
    {
        const float* o1 = g_O1 + (size_t)e*(CH*ANG*WWD);
        for (int l = tid; l < 32*5*128; l += 256) {
            int co = l / 640, r2 = l % 640;
            int v = r2 >> 7, w = r2 & 127;
            sIn[((32 + co)*5 + v)*132 + 1 + w] = o1[l];
        }
    }
    for (int l = tid; l < 64*5; l += 256) {
        sIn[l*132 + 0]   = 0.f;
        sIn[l*132 + 129] = 0.f;
    }
    int co0 = (tid >> 5) * 4;          // 0..28
    int w0  = (tid & 31) * 4;          // 0..124
    float acc[4][5][4] = {};
    for (int cc = 0; cc < 4; cc++) {
        __syncthreads();
        for (int l = tid; l < 16*32*9; l += 256) {
            int ci = l / 288, r2 = l % 288;
            int co = r2 / 9, kk = r2 % 9;
            ws[l] = w2[((size_t)co*64 + cc*16 + ci)*9 + kk];
        }
        __syncthreads();
        for (int ci = 0; ci < 16; ci++) {
            const float* inb = &sIn[(size_t)(cc*16 + ci)*5*132];
            #pragma unroll
            for (int kv = 0; kv < 3; kv++) {
                float wv[4][3];
                #pragma unroll
                for (int i = 0; i < 4; i++)
                    #pragma unroll
                    for (int kw = 0; kw < 3; kw++)
                        wv[i][kw] = ws[ci*288 + (co0 + i)*9 + kv*3 + kw];
                #pragma unroll
                for (int v = 0; v < 5; v++) {
                    int vr = v + kv - 1;
                    if (vr < 0 || vr > 4) continue;
                    float in6[6];
                    *(float4*)&in6[0] = *(const float4*)(inb + vr*132 + w0);
                    *(float2*)&in6[4] = *(const float2*)(inb + vr*132 + w0 + 4);
                    #pragma unroll
                    for (int i = 0; i < 4; i++)
                        #pragma unroll
                        for (int kw = 0; kw < 3; kw++)
                            #pragma unroll
                            for (int s = 0; s < 4; s++)
                                acc[i][v][s] += wv[i][kw]*in6[kw + s];
                }
            }
        }
    }
    #pragma unroll
    for (int i = 0; i < 4; i++)
        #pragma unroll
        for (int v = 0; v < 5; v++) {
            float4 o;
            float x;
            x = acc[i][v][0]; o.x = (x >= 0.f) ? x : 0.1f*x;
            x = acc[i][v][1]; o.y = (x >= 0.f) ? x : 0.1f*x;
            x = acc[i][v][2]; o.z = (x >= 0.f) ? x : 0.1f*x;
            x = acc[i][v][3]; o.w = (x >= 0.f) ? x : 0.1f*x;
            *(float4*)&out[(((size_t)(n*AN2 + u*ANG + v)*CH + co0 + i) << 14)
                           + h*WWD + w0] = o;
        }
}

// ================= launcher ===============================================
extern "C" void kernel_launch(void* const* d_in, const int* in_sizes, int n_in,
                              void* d_out, int out_size) {
    const float* lf = (const float*)d_in[0];
    const float* w1 = (const float*)d_in[1];
    const float* w2 = (const float*)d_in[2];
    float* out = (float*)d_out;

    cudaFuncSetAttribute(k_conv1, cudaFuncAttributeMaxDynamicSharedMemorySize, 86016);
    cudaFuncSetAttribute(k_conv2, cudaFuncAttributeMaxDynamicSharedMemorySize, 187392);

    k_permute<<<50*32*4, 256>>>(lf);
    {
        dim3 gs(PP/128, BB);
        k_sq<<<gs, 128>>>();
    }
    {
        dim3 g(55, BB);
        k_gram<<<g, 256>>>();
    }
    k_topk<<<(BB*PP)/8, 256>>>();
    k_conv1<<<NE, 256, 86016>>>(lf, w1);
    k_conv2<<<NE, 256, 187392>>>(lf, w2, out);
}

// round 15
// speedup vs baseline: 6.5916x; 6.5916x over previous
#include <cuda_runtime.h>
#include <cstdint>

#define F_INF __int_as_float(0x7f800000)

#define NN 2
#define ANG 5
#define AN2 25
#define CH 32
#define KN 6
#define PSHL 8
#define HH 128
#define WWD 128
#define PNH 16                 // WWD / PSHL
#define BB (NN*PNH)            // 32
#define CM (CH*ANG*PSHL)       // 1280
#define PP (ANG*HH)            // 640
#define NE (NN*ANG*HH)         // 1280 epi images
#define IMG (HH*WWD)           // 16384
#define NCHUNK (CM/16)         // 80
#define CAP 128
#define MARGIN 0.05f

// ---------------- scratch (device globals; no allocations) ----------------
__device__ float  g_M [(size_t)BB*CM*PP];       // k-major   (for gram/sq)
__device__ float  g_MT[(size_t)BB*PP*CM];       // p-major   (for refine)
__device__ float  g_G [(size_t)BB*PP*PP];       // fast fp32 gram, mirrored
__device__ float  g_SQF[BB*PP];                 // fused-tree fp32 sq (ref-exact)
__device__ int    g_CAND[(size_t)BB*PP*CAP];
__device__ int    g_CNT[BB*PP];
__device__ int    g_IDX[BB*PP*KN];
__device__ float  g_O1[(size_t)NE*CH*ANG*WWD];  // conv1 output

// ================= kernel 1: permute lf_fea -> M and MT ===================
__global__ void k_permute(const float* __restrict__ lf) {
    int bid = blockIdx.x;                 // (a0, c, htile)
    int ht  = bid & 3;
    int c   = (bid >> 2) & 31;
    int a0  = bid >> 7;                   // 0..49
    int n = a0 / AN2, r = a0 % AN2, u = r / ANG, v = r % ANG;
    __shared__ float s[32][129];
    const float* src = lf + ((size_t)(a0*CH + c) << 14) + (size_t)(ht*32)*WWD;
    for (int i = threadIdx.x; i < 32*128; i += 256) {
        int hh = i >> 7, w = i & 127;
        s[hh][w] = src[i];
    }
    __syncthreads();
    int cmBase = c*40 + v*8;
    for (int i = threadIdx.x; i < 128*32; i += 256) {
        int w = i >> 5, hh = i & 31;
        int pnh = w >> 3, psh = w & 7;
        int b = n*PNH + pnh;
        int cm = cmBase + psh;
        int p  = u*HH + ht*32 + hh;
        float val = s[hh][w];
        g_M [((size_t)b*CM + cm)*PP + p] = val;
        g_MT[((size_t)b*PP + p)*CM + cm] = val;
    }
}

// ================= kernel 1b: sq — XLA column-reduce (fused fma) ==========
__global__ void k_sq(void) {
    int b = blockIdx.y;
    int q = blockIdx.x*128 + threadIdx.x;
    const float* Mb = g_M + (size_t)b*CM*PP + q;
    float partial[32];
    #pragma unroll
    for (int s = 0; s < 32; s++) partial[s] = 0.f;
    #pragma unroll 2
    for (int j = 0; j < 40; j++) {
        #pragma unroll
        for (int s = 0; s < 32; s++) {
            float m = Mb[(size_t)(j*32 + s)*PP];
            partial[s] = __fmaf_rn(m, m, partial[s]);
        }
    }
    #pragma unroll
    for (int off = 16; off > 0; off >>= 1)
        #pragma unroll
        for (int s = 0; s < 16; s++)
            if (s < off)
                partial[s] = __fadd_rn(partial[s], partial[s + off]);
    g_SQF[b*PP + q] = partial[0];
}

// ================= kernel 2: FAST fp32 Gram (candidate ranking only) ======
__global__ __launch_bounds__(256) void k_gram(void) {
    int b = blockIdx.y;
    int t = blockIdx.x;                   // 0..54 -> (ti,tj), ti<=tj
    int ti = 0, rem = t;
    while (rem >= 10 - ti) { rem -= 10 - ti; ti++; }
    int tj = ti + rem;
    __shared__ float As[16][68];
    __shared__ float Bs[16][68];
    const float* Mb = g_M + (size_t)b*CM*PP;
    int tid = threadIdx.x;
    int tx = tid & 15, ty = tid >> 4;
    int pi0 = ti*64, qj0 = tj*64;
    float acc[4][4] = {};
    int lr = tid >> 4;
    int li = (tid & 15) * 4;
    for (int kk = 0; kk < CM; kk += 16) {
        const float* pA = Mb + (size_t)(kk + lr)*PP;
        *(float4*)&As[lr][li] = *(const float4*)&pA[pi0 + li];
        *(float4*)&Bs[lr][li] = *(const float4*)&pA[qj0 + li];
        __syncthreads();
        #pragma unroll
        for (int s = 0; s < 16; s++) {
            float4 a4 = *(float4*)&As[s][ty*4];
            float4 b4 = *(float4*)&Bs[s][tx*4];
            float av[4] = {a4.x, a4.y, a4.z, a4.w};
            float bv[4] = {b4.x, b4.y, b4.z, b4.w};
            #pragma unroll
            for (int i = 0; i < 4; i++)
                #pragma unroll
                for (int j = 0; j < 4; j++)
                    acc[i][j] = __fmaf_rn(av[i], bv[j], acc[i][j]);
        }
        __syncthreads();
    }
    float* Gb = g_G + (size_t)b*PP*PP;
    #pragma unroll
    for (int i = 0; i < 4; i++)
        #pragma unroll
        for (int j = 0; j < 4; j++) {
            float v = acc[i][j];
            int p = pi0 + ty*4 + i, q = qj0 + tx*4 + j;
            Gb[(size_t)p*PP + q] = v;
            Gb[(size_t)q*PP + p] = v;
        }
}

// ================= kernel 3: fast top-6 + candidate collection ============
__global__ void k_topk_cand(void) {
    int wid  = (blockIdx.x*blockDim.x + threadIdx.x) >> 5;
    int lane = threadIdx.x & 31;
    if (wid >= BB*PP) return;
    int b = wid / PP, r = wid % PP;
    const float* Gr = g_G + (size_t)b*PP*PP + (size_t)r*PP;
    const float* sq = g_SQF + b*PP;
    float sqr = sq[r];
    float lv[6]; int lq[6];
    #pragma unroll
    for (int i = 0; i < 6; i++) { lv[i] = F_INF; lq[i] = 0x7fffffff; }
    for (int q = lane; q < PP; q += 32) {
        float s1 = __fadd_rn(sqr, sq[q]);
        float tg = __fmul_rn(2.0f, Gr[q]);
        float v  = __fadd_rn(s1, -tg);
        bool ins = (v < lv[5]) || (v == lv[5] && q < lq[5]);
        if (ins) {
            lv[5] = v; lq[5] = q;
            #pragma unroll
            for (int i = 5; i > 0; i--) {
                bool sw = (lv[i] < lv[i-1]) || (lv[i] == lv[i-1] && lq[i] < lq[i-1]);
                if (sw) {
                    float tv = lv[i]; lv[i] = lv[i-1]; lv[i-1] = tv;
                    int   tq = lq[i]; lq[i] = lq[i-1]; lq[i-1] = tq;
                }
            }
        }
    }
    float kth = F_INF;
    for (int t = 0; t < 6; t++) {
        float bv = lv[0]; int bq = lq[0];
        #pragma unroll
        for (int o = 16; o; o >>= 1) {
            float v2 = __shfl_xor_sync(0xffffffffu, bv, o);
            int   q2 = __shfl_xor_sync(0xffffffffu, bq, o);
            if (v2 < bv || (v2 == bv && q2 < bq)) { bv = v2; bq = q2; }
        }
        if (lq[0] == bq) {
            #pragma unroll
            for (int i = 0; i < 5; i++) { lv[i] = lv[i+1]; lq[i] = lq[i+1]; }
            lv[5] = F_INF; lq[5] = 0x7fffffff;
        }
        if (t == 5) kth = bv;
    }
    // candidate collection: fast_d <= kth + MARGIN
    float thr = kth + MARGIN;
    int base = 0;
    int* cnd = g_CAND + (size_t)wid*CAP;
    for (int q0 = 0; q0 < PP; q0 += 32) {
        int q = q0 + lane;
        float s1 = __fadd_rn(sqr, sq[q]);
        float tg = __fmul_rn(2.0f, Gr[q]);
        float v  = __fadd_rn(s1, -tg);
        bool pred = (v <= thr);
        unsigned mask = __ballot_sync(0xffffffffu, pred);
        if (pred) {
            int pos = base + __popc(mask & ((1u << lane) - 1u));
            if (pos < CAP) cnd[pos] = q;
        }
        base += __popc(mask);
    }
    if (lane == 0) g_CNT[wid] = (base < CAP) ? base : CAP;
}

// ================= kernel 4: refine — bit-exact chunked-G d + top-6 =======
// Recomputes d for candidates with the reference-matching recipe: fp64-exact
// 16-k chunks in ascending order, one fp32 rounding per chunk fold, then the
// quantized fp32 d op sequence on the fused-tree sq. Ties -> lower index.
__global__ __launch_bounds__(256) void k_refine(void) {
    int wip  = threadIdx.x >> 5, lane = threadIdx.x & 31;
    int row  = blockIdx.x*8 + wip;
    if (row >= BB*PP) return;
    int b = row / PP, r = row % PP;
    __shared__ float sV[8][CAP];
    __shared__ int   sQ[8][CAP];
    int cnt = g_CNT[row];
    const float* MTb = g_MT + (size_t)b*PP*CM;
    const float* Mr  = MTb + (size_t)r*CM;
    // preload this row's chunks: lane handles chunks j = lane, lane+32, lane+64
    float mr[3][16];
    #pragma unroll
    for (int cj = 0; cj < 3; cj++) {
        int j = lane + cj*32;
        if (j < NCHUNK) {
            #pragma unroll
            for (int t4 = 0; t4 < 4; t4++)
                *(float4*)&mr[cj][t4*4] = *(const float4*)&Mr[j*16 + t4*4];
        }
    }
    const float* sq = g_SQF + b*PP;
    float sqr = sq[r];
    const int* cnd = g_CAND + (size_t)row*CAP;
    for (int ci = 0; ci < cnt; ci++) {
        int q = cnd[ci];
        const float* Mq = MTb + (size_t)q*CM;
        double ch[3] = {0.0, 0.0, 0.0};
        #pragma unroll
        for (int cj = 0; cj < 3; cj++) {
            int j = lane + cj*32;
            if (j < NCHUNK) {
                float mq[16];
                #pragma unroll
                for (int t4 = 0; t4 < 4; t4++)
                    *(float4*)&mq[t4*4] = *(const float4*)&Mq[j*16 + t4*4];
                #pragma unroll
                for (int t = 0; t < 16; t++)
                    ch[cj] = fma((double)mr[cj][t], (double)mq[t], ch[cj]);
            }
        }
        // ascending serial fold with one fp32 rounding per chunk
        float acc32 = 0.f;
        for (int j = 0; j < NCHUNK; j++) {
            double chv = __shfl_sync(0xffffffffu, ch[j >> 5], j & 31);
            acc32 = (float)((double)acc32 + chv);
        }
        float s1 = __fadd_rn(sqr, sq[q]);
        float tg = __fmul_rn(2.0f, acc32);
        float v  = __fadd_rn(s1, -tg);
        if (lane == 0) { sV[wip][ci] = v; sQ[wip][ci] = q; }
    }
    __syncwarp();
    if (lane == 0) {
        for (int t = 0; t < 6; t++) {
            float bv = F_INF; int bq = 0x7fffffff; int bi = -1;
            for (int ci = 0; ci < cnt; ci++) {
                float v = sV[wip][ci]; int q = sQ[wip][ci];
                if (v < bv || (v == bv && q < bq)) { bv = v; bq = q; bi = ci; }
            }
            g_IDX[(size_t)row*KN + t] = bq;
            if (bi >= 0) { sV[wip][bi] = F_INF; sQ[wip][bi] = 0x7fffffff; }
        }
    }
}

// ================= kernel 5: gather + 1x1 conv + leaky -> O1 ==============
__global__ __launch_bounds__(256) void k_conv1(const float* __restrict__ lf,
                                               const float* __restrict__ w1) {
    int e = blockIdx.x;
    int n = e / (ANG*HH);
    int rr_ = e % (ANG*HH);
    int u = rr_ / HH, h = rr_ % HH;
    extern __shared__ float sm[];
    float* Xs = sm;                 // [32][640]
    float* Ws = sm + 32*640;        // [ci][co]
    __shared__ int nbU[PNH][KN], nbH[PNH][KN];
    int tid = threadIdx.x;
    if (tid < PNH*KN) {
        int pnh = tid / KN, k = tid % KN;
        int b = n*PNH + pnh;
        int q = g_IDX[((size_t)b*PP + u*HH + h)*KN + k];
        nbU[pnh][k] = q >> 7;
        nbH[pnh][k] = q & 127;
    }
    int co0  = (tid >> 6) << 3;
    int col0 = (tid & 63) * 10;
    float acc[8][10] = {};
    for (int k = 0; k < KN; k++) {
        __syncthreads();
        for (int l = tid; l < 1024; l += 256) {
            int ci = l >> 5, co = l & 31;
            Ws[ci*32 + co] = w1[co*(CH*KN) + k*CH + ci];
        }
        for (int seg = tid; seg < 32*5*16; seg += 256) {
            int ci = seg / 80;
            int r2 = seg % 80;
            int v = r2 >> 4, pnh = r2 & 15;
            int uu = nbU[pnh][k], hh2 = nbH[pnh][k];
            const float* src = lf + (((size_t)(n*AN2 + uu*ANG + v)*CH + ci) << 14)
                                  + hh2*WWD + pnh*PSHL;
            float4 x0 = *(const float4*)src;
            float4 x1 = *(const float4*)(src + 4);
            float* dst = &Xs[ci*640 + v*128 + pnh*8];
            *(float4*)dst = x0;
            *(float4*)(dst + 4) = x1;
        }
        __syncthreads();
        #pragma unroll 4
        for (int ci = 0; ci < 32; ci++) {
            float w8[8];
            *(float4*)&w8[0] = *(float4*)&Ws[ci*32 + co0];
            *(float4*)&w8[4] = *(float4*)&Ws[ci*32 + co0 + 4];
            float x10[10];
            #pragma unroll
            for (int s = 0; s < 5; s++)
                *(float2*)&x10[2*s] = *(float2*)&Xs[ci*640 + col0 + 2*s];
            #pragma unroll
            for (int i = 0; i < 8; i++)
                #pragma unroll
                for (int s = 0; s < 10; s++)
                    acc[i][s] += w8[i]*x10[s];
        }
    }
    float* dst = g_O1 + (size_t)e*(CH*ANG*WWD);
    #pragma unroll
    for (int i = 0; i < 8; i++)
        #pragma unroll
        for (int s = 0; s < 10; s++) {
            float x = acc[i][s];
            dst[(co0 + i)*640 + col0 + s] = (x >= 0.f) ? x : 0.1f*x;
        }
}

// ================= kernel 6: concat + 3x3 conv + leaky + out-permute ======
__global__ __launch_bounds__(256,1) void k_conv2(const float* __restrict__ lf,
                                                 const float* __restrict__ w2,
                                                 float* __restrict__ out) {
    int e = blockIdx.x;
    int n = e / (ANG*HH);
    int rr_ = e % (ANG*HH);
    int u = rr_ / HH, h = rr_ % HH;
    extern __shared__ float sm[];
    float* sIn = sm;                      // [64][5][132]
    float* ws  = sm + 64*5*132;           // [16][32][9]
    int tid = threadIdx.x;
    for (int l = tid; l < 32*5*128; l += 256) {
        int row = l >> 7, w = l & 127;
        int c = row / 5, v = row % 5;
        sIn[(c*5 + v)*132 + 1 + w] =
            lf[(((size_t)(n*AN2 + u*ANG + v)*CH + c) << 14) + h*WWD + w];
    }
    {
        const float* o1 = g_O1 + (size_t)e*(CH*ANG*WWD);
        for (int l = tid; l < 32*5*128; l += 256) {
            int co = l / 640, r2 = l % 640;
            int v = r2 >> 7, w = r2 & 127;
            sIn[((32 + co)*5 + v)*132 + 1 + w] = o1[l];
        }
    }
    for (int l = tid; l < 64*5; l += 256) {
        sIn[l*132 + 0]   = 0.f;
        sIn[l*132 + 129] = 0.f;
    }
    int co0 = (tid >> 5) * 4;
    int w0  = (tid & 31) * 4;
    float acc[4][5][4] = {};
    for (int cc = 0; cc < 4; cc++) {
        __syncthreads();
        for (int l = tid; l < 16*32*9; l += 256) {
            int ci = l / 288, r2 = l % 288;
            int co = r2 / 9, kk = r2 % 9;
            ws[l] = w2[((size_t)co*64 + cc*16 + ci)*9 + kk];
        }
        __syncthreads();
        for (int ci = 0; ci < 16; ci++) {
            const float* inb = &sIn[(size_t)(cc*16 + ci)*5*132];
            #pragma unroll
            for (int kv = 0; kv < 3; kv++) {
                float wv[4][3];
                #pragma unroll
                for (int i = 0; i < 4; i++)
                    #pragma unroll
                    for (int kw = 0; kw < 3; kw++)
                        wv[i][kw] = ws[ci*288 + (co0 + i)*9 + kv*3 + kw];
                #pragma unroll
                for (int v = 0; v < 5; v++) {
                    int vr = v + kv - 1;
                    if (vr < 0 || vr > 4) continue;
                    float in6[6];
                    *(float4*)&in6[0] = *(const float4*)(inb + vr*132 + w0);
                    *(float2*)&in6[4] = *(const float2*)(inb + vr*132 + w0 + 4);
                    #pragma unroll
                    for (int i = 0; i < 4; i++)
                        #pragma unroll
                        for (int kw = 0; kw < 3; kw++)
                            #pragma unroll
                            for (int s = 0; s < 4; s++)
                                acc[i][v][s] += wv[i][kw]*in6[kw + s];
                }
            }
        }
    }
    #pragma unroll
    for (int i = 0; i < 4; i++)
        #pragma unroll
        for (int v = 0; v < 5; v++) {
            float4 o;
            float x;
            x = acc[i][v][0]; o.x = (x >= 0.f) ? x : 0.1f*x;
            x = acc[i][v][1]; o.y = (x >= 0.f) ? x : 0.1f*x;
            x = acc[i][v][2]; o.z = (x >= 0.f) ? x : 0.1f*x;
            x = acc[i][v][3]; o.w = (x >= 0.f) ? x : 0.1f*x;
            *(float4*)&out[(((size_t)(n*AN2 + u*ANG + v)*CH + co0 + i) << 14)
                           + h*WWD + w0] = o;
        }
}

// ================= launcher ===============================================
extern "C" void kernel_launch(void* const* d_in, const int* in_sizes, int n_in,
                              void* d_out, int out_size) {
    const float* lf = (const float*)d_in[0];
    const float* w1 = (const float*)d_in[1];
    const float* w2 = (const float*)d_in[2];
    float* out = (float*)d_out;

    cudaFuncSetAttribute(k_conv1, cudaFuncAttributeMaxDynamicSharedMemorySize, 86016);
    cudaFuncSetAttribute(k_conv2, cudaFuncAttributeMaxDynamicSharedMemorySize, 187392);

    k_permute<<<50*32*4, 256>>>(lf);
    {
        dim3 gs(PP/128, BB);
        k_sq<<<gs, 128>>>();
    }
    {
        dim3 g(55, BB);
        k_gram<<<g, 256>>>();
    }
    k_topk_cand<<<(BB*PP)/8, 256>>>();
    k_refine<<<(BB*PP)/8, 256>>>();
    k_conv1<<<NE, 256, 86016>>>(lf, w1);
    k_conv2<<<NE, 256, 187392>>>(lf, w2, out);
}

// round 17
// speedup vs baseline: 6.6259x; 1.0052x over previous
#include <cuda_runtime.h>
#include <cstdint>

#define F_INF __int_as_float(0x7f800000)

#define NN 2
#define ANG 5
#define AN2 25
#define CH 32
#define KN 6
#define PSHL 8
#define HH 128
#define WWD 128
#define PNH 16                 // WWD / PSHL
#define BB (NN*PNH)            // 32
#define CM (CH*ANG*PSHL)       // 1280
#define PP (ANG*HH)            // 640
#define NE (NN*ANG*HH)         // 1280 epi images
#define IMG (HH*WWD)           // 16384
#define NCHUNK (CM/16)         // 80
#define CAP 128
#define MARGIN 0.05f

typedef unsigned long long ull;

// -------- packed f32x2 helpers (bit-identical per-lane IEEE fp32) ---------
__device__ __forceinline__ ull pk2(float lo, float hi) {
    ull r; asm("mov.b64 %0, {%1, %2};" : "=l"(r) : "f"(lo), "f"(hi)); return r;
}
__device__ __forceinline__ void upk2(ull v, float& lo, float& hi) {
    asm("mov.b64 {%0, %1}, %2;" : "=f"(lo), "=f"(hi) : "l"(v));
}
__device__ __forceinline__ ull dup2(float x) { return pk2(x, x); }
__device__ __forceinline__ ull fma2(ull a, ull b, ull c) {
    ull d; asm("fma.rn.f32x2 %0, %1, %2, %3;" : "=l"(d) : "l"(a), "l"(b), "l"(c));
    return d;
}

// ---------------- scratch (device globals; no allocations) ----------------
__device__ float  g_M [(size_t)BB*CM*PP];       // k-major   (for gram/sq)
__device__ float  g_MT[(size_t)BB*PP*CM];       // p-major   (for refine)
__device__ float  g_G [(size_t)BB*PP*PP];       // fast fp32 gram, mirrored
__device__ float  g_SQF[BB*PP];                 // fused-tree fp32 sq (ref-exact)
__device__ int    g_CAND[(size_t)BB*PP*CAP];
__device__ int    g_CNT[BB*PP];
__device__ int    g_IDX[BB*PP*KN];
__device__ float  g_O1[(size_t)NE*CH*ANG*WWD];  // conv1 output

// ================= kernel 1: permute lf_fea -> M and MT ===================
__global__ void k_permute(const float* __restrict__ lf) {
    int bid = blockIdx.x;                 // (a0, c, htile)
    int ht  = bid & 3;
    int c   = (bid >> 2) & 31;
    int a0  = bid >> 7;                   // 0..49
    int n = a0 / AN2, r = a0 % AN2, u = r / ANG, v = r % ANG;
    __shared__ float s[32][129];
    const float* src = lf + ((size_t)(a0*CH + c) << 14) + (size_t)(ht*32)*WWD;
    for (int i = threadIdx.x; i < 32*128; i += 256) {
        int hh = i >> 7, w = i & 127;
        s[hh][w] = src[i];
    }
    __syncthreads();
    int cmBase = c*40 + v*8;
    for (int i = threadIdx.x; i < 128*32; i += 256) {
        int w = i >> 5, hh = i & 31;
        int pnh = w >> 3, psh = w & 7;
        int b = n*PNH + pnh;
        int cm = cmBase + psh;
        int p  = u*HH + ht*32 + hh;
        float val = s[hh][w];
        g_M [((size_t)b*CM + cm)*PP + p] = val;
        g_MT[((size_t)b*PP + p)*CM + cm] = val;
    }
}

// ================= kernel 1b: sq — XLA column-reduce (fused fma) ==========
__global__ void k_sq(void) {
    int b = blockIdx.y;
    int q = blockIdx.x*128 + threadIdx.x;
    const float* Mb = g_M + (size_t)b*CM*PP + q;
    float partial[32];
    #pragma unroll
    for (int s = 0; s < 32; s++) partial[s] = 0.f;
    #pragma unroll 2
    for (int j = 0; j < 40; j++) {
        #pragma unroll
        for (int s = 0; s < 32; s++) {
            float m = Mb[(size_t)(j*32 + s)*PP];
            partial[s] = __fmaf_rn(m, m, partial[s]);
        }
    }
    #pragma unroll
    for (int off = 16; off > 0; off >>= 1)
        #pragma unroll
        for (int s = 0; s < 16; s++)
            if (s < off)
                partial[s] = __fadd_rn(partial[s], partial[s + off]);
    g_SQF[b*PP + q] = partial[0];
}

// ================= kernel 2: FAST fp32 Gram — 128x128 tiles, f32x2 ========
// Swizzle SW(g) = g ^ (g>>3) on 16B granules: conflict-free smem loads.
__global__ __launch_bounds__(256) void k_gram(void) {
    int b = blockIdx.y;
    int t = blockIdx.x;                   // 0..14 -> (ti,tj) over 5, ti<=tj
    int ti = 0, rem = t;
    while (rem >= 5 - ti) { rem -= 5 - ti; ti++; }
    int tj = ti + rem;
    __shared__ float As[16*128];
    __shared__ float Bs[16*128];
    const float* Mb = g_M + (size_t)b*CM*PP;
    int tid = threadIdx.x;
    int tx = tid & 15, ty = tid >> 4;
    int pi0 = ti*128, qj0 = tj*128;
    int lr = tid >> 4;                    // smem row for store
    int lc = tid & 15;                    // granule base for store
    int g0 = lc, g1 = lc + 16;
    int sw0 = (g0 ^ (g0 >> 3))*4, sw1 = (g1 ^ (g1 >> 3))*4;
    int ga0 = ((ty*2)     ^ ((ty*2)     >> 3))*4;
    int ga1 = ((ty*2 + 1) ^ ((ty*2 + 1) >> 3))*4;
    int gb0 = ((tx*2)     ^ ((tx*2)     >> 3))*4;
    int gb1 = ((tx*2 + 1) ^ ((tx*2 + 1) >> 3))*4;
    ull accp[8][4];
    #pragma unroll
    for (int i = 0; i < 8; i++)
        #pragma unroll
        for (int j = 0; j < 4; j++) accp[i][j] = 0ull;
    for (int kk = 0; kk < CM; kk += 16) {
        const float* pA = Mb + (size_t)(kk + lr)*PP;
        *(float4*)&As[lr*128 + sw0] = *(const float4*)&pA[pi0 + g0*4];
        *(float4*)&As[lr*128 + sw1] = *(const float4*)&pA[pi0 + g1*4];
        *(float4*)&Bs[lr*128 + sw0] = *(const float4*)&pA[qj0 + g0*4];
        *(float4*)&Bs[lr*128 + sw1] = *(const float4*)&pA[qj0 + g1*4];
        __syncthreads();
        #pragma unroll
        for (int s = 0; s < 16; s++) {
            float4 a40 = *(float4*)&As[s*128 + ga0];
            float4 a41 = *(float4*)&As[s*128 + ga1];
            float4 b40 = *(float4*)&Bs[s*128 + gb0];
            float4 b41 = *(float4*)&Bs[s*128 + gb1];
            ull bp[4];
            bp[0] = pk2(b40.x, b40.y); bp[1] = pk2(b40.z, b40.w);
            bp[2] = pk2(b41.x, b41.y); bp[3] = pk2(b41.z, b41.w);
            float av[8] = {a40.x, a40.y, a40.z, a40.w, a41.x, a41.y, a41.z, a41.w};
            #pragma unroll
            for (int i = 0; i < 8; i++) {
                ull ad = dup2(av[i]);
                #pragma unroll
                for (int j = 0; j < 4; j++)
                    accp[i][j] = fma2(ad, bp[j], accp[i][j]);
            }
        }
        __syncthreads();
    }
    float* Gb = g_G + (size_t)b*PP*PP;
    #pragma unroll
    for (int i = 0; i < 8; i++) {
        float o[8];
        #pragma unroll
        for (int j = 0; j < 4; j++) upk2(accp[i][j], o[2*j], o[2*j + 1]);
        int p = pi0 + ty*8 + i;
        float* row = &Gb[(size_t)p*PP + qj0 + tx*8];
        *(float4*)&row[0] = *(float4*)&o[0];
        *(float4*)&row[4] = *(float4*)&o[4];
        #pragma unroll
        for (int j = 0; j < 8; j++)
            Gb[(size_t)(qj0 + tx*8 + j)*PP + p] = o[j];   // mirror
    }
}

// ================= kernel 3: fast top-6 + candidate collection ============
__global__ void k_topk_cand(void) {
    int wid  = (blockIdx.x*blockDim.x + threadIdx.x) >> 5;
    int lane = threadIdx.x & 31;
    if (wid >= BB*PP) return;
    int b = wid / PP, r = wid % PP;
    const float* Gr = g_G + (size_t)b*PP*PP + (size_t)r*PP;
    const float* sq = g_SQF + b*PP;
    float sqr = sq[r];
    float lv[6]; int lq[6];
    #pragma unroll
    for (int i = 0; i < 6; i++) { lv[i] = F_INF; lq[i] = 0x7fffffff; }
    for (int q = lane; q < PP; q += 32) {
        float s1 = __fadd_rn(sqr, sq[q]);
        float tg = __fmul_rn(2.0f, Gr[q]);
        float v  = __fadd_rn(s1, -tg);
        bool ins = (v < lv[5]) || (v == lv[5] && q < lq[5]);
        if (ins) {
            lv[5] = v; lq[5] = q;
            #pragma unroll
            for (int i = 5; i > 0; i--) {
                bool sw = (lv[i] < lv[i-1]) || (lv[i] == lv[i-1] && lq[i] < lq[i-1]);
                if (sw) {
                    float tv = lv[i]; lv[i] = lv[i-1]; lv[i-1] = tv;
                    int   tq = lq[i]; lq[i] = lq[i-1]; lq[i-1] = tq;
                }
            }
        }
    }
    float kth = F_INF;
    for (int t = 0; t < 6; t++) {
        float bv = lv[0]; int bq = lq[0];
        #pragma unroll
        for (int o = 16; o; o >>= 1) {
            float v2 = __shfl_xor_sync(0xffffffffu, bv, o);
            int   q2 = __shfl_xor_sync(0xffffffffu, bq, o);
            if (v2 < bv || (v2 == bv && q2 < bq)) { bv = v2; bq = q2; }
        }
        if (lq[0] == bq) {
            #pragma unroll
            for (int i = 0; i < 5; i++) { lv[i] = lv[i+1]; lq[i] = lq[i+1]; }
            lv[5] = F_INF; lq[5] = 0x7fffffff;
        }
        if (t == 5) kth = bv;
    }
    float thr = kth + MARGIN;
    int base = 0;
    int* cnd = g_CAND + (size_t)wid*CAP;
    for (int q0 = 0; q0 < PP; q0 += 32) {
        int q = q0 + lane;
        float s1 = __fadd_rn(sqr, sq[q]);
        float tg = __fmul_rn(2.0f, Gr[q]);
        float v  = __fadd_rn(s1, -tg);
        bool pred = (v <= thr);
        unsigned mask = __ballot_sync(0xffffffffu, pred);
        if (pred) {
            int pos = base + __popc(mask & ((1u << lane) - 1u));
            if (pos < CAP) cnd[pos] = q;
        }
        base += __popc(mask);
    }
    if (lane == 0) g_CNT[wid] = (base < CAP) ? base : CAP;
}

// ================= kernel 4: refine — bit-exact chunked-G d + top-6 =======
__global__ __launch_bounds__(256) void k_refine(void) {
    int wip  = threadIdx.x >> 5, lane = threadIdx.x & 31;
    int row  = blockIdx.x*8 + wip;
    if (row >= BB*PP) return;
    int b = row / PP, r = row % PP;
    __shared__ float sV[8][CAP];
    __shared__ int   sQ[8][CAP];
    int cnt = g_CNT[row];
    const float* MTb = g_MT + (size_t)b*PP*CM;
    const float* Mr  = MTb + (size_t)r*CM;
    float mr[3][16];
    #pragma unroll
    for (int cj = 0; cj < 3; cj++) {
        int j = lane + cj*32;
        if (j < NCHUNK) {
            #pragma unroll
            for (int t4 = 0; t4 < 4; t4++)
                *(float4*)&mr[cj][t4*4] = *(const float4*)&Mr[j*16 + t4*4];
        }
    }
    const float* sq = g_SQF + b*PP;
    float sqr = sq[r];
    const int* cnd = g_CAND + (size_t)row*CAP;
    for (int ci = 0; ci < cnt; ci++) {
        int q = cnd[ci];
        const float* Mq = MTb + (size_t)q*CM;
        double ch[3] = {0.0, 0.0, 0.0};
        #pragma unroll
        for (int cj = 0; cj < 3; cj++) {
            int j = lane + cj*32;
            if (j < NCHUNK) {
                float mq[16];
                #pragma unroll
                for (int t4 = 0; t4 < 4; t4++)
                    *(float4*)&mq[t4*4] = *(const float4*)&Mq[j*16 + t4*4];
                #pragma unroll
                for (int t = 0; t < 16; t++)
                    ch[cj] = fma((double)mr[cj][t], (double)mq[t], ch[cj]);
            }
        }
        float acc32 = 0.f;
        for (int j = 0; j < NCHUNK; j++) {
            double chv = __shfl_sync(0xffffffffu, ch[j >> 5], j & 31);
            acc32 = (float)((double)acc32 + chv);
        }
        float s1 = __fadd_rn(sqr, sq[q]);
        float tg = __fmul_rn(2.0f, acc32);
        float v  = __fadd_rn(s1, -tg);
        if (lane == 0) { sV[wip][ci] = v; sQ[wip][ci] = q; }
    }
    __syncwarp();
    if (lane == 0) {
        for (int t = 0; t < 6; t++) {
            float bv = F_INF; int bq = 0x7fffffff; int bi = -1;
            for (int ci = 0; ci < cnt; ci++) {
                float v = sV[wip][ci]; int q = sQ[wip][ci];
                if (v < bv || (v == bv && q < bq)) { bv = v; bq = q; bi = ci; }
            }
            g_IDX[(size_t)row*KN + t] = bq;
            if (bi >= 0) { sV[wip][bi] = F_INF; sQ[wip][bi] = 0x7fffffff; }
        }
    }
}

// ================= kernel 5: gather + 1x1 conv + leaky -> O1 (f32x2) ======
__global__ __launch_bounds__(256) void k_conv1(const float* __restrict__ lf,
                                               const float* __restrict__ w1) {
    int e = blockIdx.x;
    int n = e / (ANG*HH);
    int rr_ = e % (ANG*HH);
    int u = rr_ / HH, h = rr_ % HH;
    extern __shared__ float sm[];
    float* Xs = sm;                 // [32][640]
    float* Ws = sm + 32*640;        // [ci][co]
    __shared__ int nbU[PNH][KN], nbH[PNH][KN];
    int tid = threadIdx.x;
    if (tid < PNH*KN) {
        int pnh = tid / KN, k = tid % KN;
        int b = n*PNH + pnh;
        int q = g_IDX[((size_t)b*PP + u*HH + h)*KN + k];
        nbU[pnh][k] = q >> 7;
        nbH[pnh][k] = q & 127;
    }
    int co0  = (tid >> 6) << 3;
    int col0 = (tid & 63) * 10;
    ull accp[8][5];
    #pragma unroll
    for (int i = 0; i < 8; i++)
        #pragma unroll
        for (int s = 0; s < 5; s++) accp[i][s] = 0ull;
    for (int k = 0; k < KN; k++) {
        __syncthreads();
        for (int l = tid; l < 1024; l += 256) {
            int ci = l >> 5, co = l & 31;
            Ws[ci*32 + co] = w1[co*(CH*KN) + k*CH + ci];
        }
        for (int seg = tid; seg < 32*5*16; seg += 256) {
            int ci = seg / 80;
            int r2 = seg % 80;
            int v = r2 >> 4, pnh = r2 & 15;
            int uu = nbU[pnh][k], hh2 = nbH[pnh][k];
            const float* src = lf + (((size_t)(n*AN2 + uu*ANG + v)*CH + ci) << 14)
                                  + hh2*WWD + pnh*PSHL;
            float4 x0 = *(const float4*)src;
            float4 x1 = *(const float4*)(src + 4);
            float* dst = &Xs[ci*640 + v*128 + pnh*8];
            *(float4*)dst = x0;
            *(float4*)(dst + 4) = x1;
        }
        __syncthreads();
        #pragma unroll 4
        for (int ci = 0; ci < 32; ci++) {
            float w8[8];
            *(float4*)&w8[0] = *(float4*)&Ws[ci*32 + co0];
            *(float4*)&w8[4] = *(float4*)&Ws[ci*32 + co0 + 4];
            ull wd[8];
            #pragma unroll
            for (int i = 0; i < 8; i++) wd[i] = dup2(w8[i]);
            ull x5[5];
            #pragma unroll
            for (int s = 0; s < 5; s++)
                x5[s] = *(const ull*)&Xs[ci*640 + col0 + 2*s];
            #pragma unroll
            for (int i = 0; i < 8; i++)
                #pragma unroll
                for (int s = 0; s < 5; s++)
                    accp[i][s] = fma2(wd[i], x5[s], accp[i][s]);
        }
    }
    float* dst = g_O1 + (size_t)e*(CH*ANG*WWD);
    #pragma unroll
    for (int i = 0; i < 8; i++)
        #pragma unroll
        for (int s = 0; s < 5; s++) {
            float lo, hi;
            upk2(accp[i][s], lo, hi);
            lo = (lo >= 0.f) ? lo : 0.1f*lo;
            hi = (hi >= 0.f) ? hi : 0.1f*hi;
            dst[(co0 + i)*640 + col0 + 2*s]     = lo;
            dst[(co0 + i)*640 + col0 + 2*s + 1] = hi;
        }
}

// ================= kernel 6: concat + 3x3 conv + leaky (f32x2) ============
__global__ __launch_bounds__(256,1) void k_conv2(const float* __restrict__ lf,
                                                 const float* __restrict__ w2,
                                                 float* __restrict__ out) {
    int e = blockIdx.x;
    int n = e / (ANG*HH);
    int rr_ = e % (ANG*HH);
    int u = rr_ / HH, h = rr_ % HH;
    extern __shared__ float sm[];
    float* sIn = sm;                      // [64][5][132]
    float* ws  = sm + 64*5*132;           // [16][32][9]
    int tid = threadIdx.x;
    for (int l = tid; l < 32*5*128; l += 256) {
        int row = l >> 7, w = l & 127;
        int c = row / 5, v = row % 5;
        sIn[(c*5 + v)*132 + 1 + w] =
            lf[(((size_t)(n*AN2 + u*ANG + v)*CH + c) << 14) + h*WWD + w];
    }
    {
        const float* o1 = g_O1 + (size_t)e*(CH*ANG*WWD);
        for (int l = tid; l < 32*5*128; l += 256) {
            int co = l / 640, r2 = l % 640;
            int v = r2 >> 7, w = r2 & 127;
            sIn[((32 + co)*5 + v)*132 + 1 + w] = o1[l];
        }
    }
    for (int l = tid; l < 64*5; l += 256) {
        sIn[l*132 + 0]   = 0.f;
        sIn[l*132 + 129] = 0.f;
    }
    int co0 = (tid >> 5) * 4;
    int w0  = (tid & 31) * 4;
    ull accp[4][5][2];
    #pragma unroll
    for (int i = 0; i < 4; i++)
        #pragma unroll
        for (int v = 0; v < 5; v++) { accp[i][v][0] = 0ull; accp[i][v][1] = 0ull; }
    for (int cc = 0; cc < 4; cc++) {
        __syncthreads();
        for (int l = tid; l < 16*32*9; l += 256) {
            int ci = l / 288, r2 = l % 288;
            int co = r2 / 9, kk = r2 % 9;
            ws[l] = w2[((size_t)co*64 + cc*16 + ci)*9 + kk];
        }
        __syncthreads();
        for (int ci = 0; ci < 16; ci++) {
            const float* inb = &sIn[(size_t)(cc*16 + ci)*5*132];
            #pragma unroll
            for (int kv = 0; kv < 3; kv++) {
                ull wd[4][3];
                #pragma unroll
                for (int i = 0; i < 4; i++)
                    #pragma unroll
                    for (int kw = 0; kw < 3; kw++)
                        wd[i][kw] = dup2(ws[ci*288 + (co0 + i)*9 + kv*3 + kw]);
                #pragma unroll
                for (int v = 0; v < 5; v++) {
                    int vr = v + kv - 1;
                    if (vr < 0 || vr > 4) continue;
                    float in6[6];
                    *(float4*)&in6[0] = *(const float4*)(inb + vr*132 + w0);
                    *(float2*)&in6[4] = *(const float2*)(inb + vr*132 + w0 + 4);
                    ull p01 = pk2(in6[0], in6[1]);
                    ull p12 = pk2(in6[1], in6[2]);
                    ull p23 = pk2(in6[2], in6[3]);
                    ull p34 = pk2(in6[3], in6[4]);
                    ull p45 = pk2(in6[4], in6[5]);
                    #pragma unroll
                    for (int i = 0; i < 4; i++) {
                        accp[i][v][0] = fma2(wd[i][0], p01, accp[i][v][0]);
                        accp[i][v][0] = fma2(wd[i][1], p12, accp[i][v][0]);
                        accp[i][v][0] = fma2(wd[i][2], p23, accp[i][v][0]);
                        accp[i][v][1] = fma2(wd[i][0], p23, accp[i][v][1]);
                        accp[i][v][1] = fma2(wd[i][1], p34, accp[i][v][1]);
                        accp[i][v][1] = fma2(wd[i][2], p45, accp[i][v][1]);
                    }
                }
            }
        }
    }
    #pragma unroll
    for (int i = 0; i < 4; i++)
        #pragma unroll
        for (int v = 0; v < 5; v++) {
            float o[4];
            upk2(accp[i][v][0], o[0], o[1]);
            upk2(accp[i][v][1], o[2], o[3]);
            float4 ov;
            ov.x = (o[0] >= 0.f) ? o[0] : 0.1f*o[0];
            ov.y = (o[1] >= 0.f) ? o[1] : 0.1f*o[1];
            ov.z = (o[2] >= 0.f) ? o[2] : 0.1f*o[2];
            ov.w = (o[3] >= 0.f) ? o[3] : 0.1f*o[3];
            *(float4*)&out[(((size_t)(n*AN2 + u*ANG + v)*CH + co0 + i) << 14)
                           + h*WWD + w0] = ov;
        }
}

// ================= launcher ===============================================
extern "C" void kernel_launch(void* const* d_in, const int* in_sizes, int n_in,
                              void* d_out, int out_size) {
    const float* lf = (const float*)d_in[0];
    const float* w1 = (const float*)d_in[1];
    const float* w2 = (const float*)d_in[2];
    float* out = (float*)d_out;

    cudaFuncSetAttribute(k_conv1, cudaFuncAttributeMaxDynamicSharedMemorySize, 86016);
    cudaFuncSetAttribute(k_conv2, cudaFuncAttributeMaxDynamicSharedMemorySize, 187392);

    k_permute<<<50*32*4, 256>>>(lf);
    {
        dim3 gs(PP/128, BB);
        k_sq<<<gs, 128>>>();
    }
    {
        dim3 g(15, BB);
        k_gram<<<g, 256>>>();
    }
    k_topk_cand<<<(BB*PP)/8, 256>>>();
    k_refine<<<(BB*PP)/8, 256>>>();
    k_conv1<<<NE, 256, 86016>>>(lf, w1);
    k_conv2<<<NE, 256, 187392>>>(lf, w2, out);
}